// round 12
// baseline (speedup 1.0000x reference)
#include <cuda_runtime.h>
#include <stdint.h>

#define BB 4
#define SS 2048
#define DD 1024
#define EE 64
#define CC 64
#define ROWS (BB*SS)          // 8192
#define NOISE_SCALE (1.0f/64.0f)
#define HALF ((size_t)BB*SS*EE*CC)      // elements per output array

// Dynamic smem layout for gemm (floats):
#define AS_STRIDE 68
#define AS_FLOATS (2*64*AS_STRIDE)      // 8704
#define WS_FLOATS (2*64*64)             // 8192
#define SMEM_FLOATS (AS_FLOATS + WS_FLOATS)
#define SMEM_BYTES (SMEM_FLOATS*4)      // 67584

// Scratch: gates transposed [b][e][s]  (2 MB)
__device__ float g_gatesT[(size_t)BB*EE*SS];

__device__ __forceinline__ void cp_async16(uint32_t dst_smem, const void* src) {
    asm volatile("cp.async.cg.shared.global [%0], [%1], 16;" :: "r"(dst_smem), "l"(src));
}

// ---------------------------------------------------------------------------
// Kernel 1: GEMM + noise + softmax -> gatesT (unchanged from R11 win:
// 64x64 tile, 4x4 thread tile, k ascending single accumulator -> gates
// bit-identical to reference ranking; cp.async double-buffered tiles).
// ---------------------------------------------------------------------------
__global__ __launch_bounds__(256)
void gemm_softmax_kernel(const float* __restrict__ X,
                         const float* __restrict__ W,
                         const float* __restrict__ noise)
{
    extern __shared__ float smem[];
    float* sA = smem;               // [2][64][AS_STRIDE]
    float* sW = smem + AS_FLOATS;   // [2][64][64]

    const int tid  = threadIdx.x;
    const int tx   = tid & 15;
    const int ty   = tid >> 4;
    const int row0 = blockIdx.x * 64;

    uint32_t smem_u32 = (uint32_t)__cvta_generic_to_shared(smem);
    const uint32_t a_base = smem_u32;
    const uint32_t w_base = smem_u32 + AS_FLOATS * 4;

    const int lr = tid >> 4;
    const int lc = (tid & 15) * 4;

    {
        const int k0 = 0;
#pragma unroll
        for (int p = 0; p < 4; p++) {
            int r = lr + p * 16;
            cp_async16(a_base + (uint32_t)((r * AS_STRIDE + lc) * 4),
                       &X[(size_t)(row0 + r) * DD + k0 + lc]);
        }
#pragma unroll
        for (int p = 0; p < 4; p++) {
            int kk = lr + p * 16;
            cp_async16(w_base + (uint32_t)((kk * 64 + lc) * 4),
                       &W[(size_t)(k0 + kk) * EE + lc]);
        }
        asm volatile("cp.async.commit_group;");
    }

    float acc[4][4];
#pragma unroll
    for (int i = 0; i < 4; i++)
#pragma unroll
        for (int j = 0; j < 4; j++) acc[i][j] = 0.0f;

    for (int it = 0; it < 16; it++) {
        const int buf = it & 1;

        asm volatile("cp.async.wait_group 0;");
        __syncthreads();

        if (it < 15) {
            const int k1 = (it + 1) * 64;
            const int nb = buf ^ 1;
            const uint32_t a_off = a_base + (uint32_t)(nb * 64 * AS_STRIDE * 4);
            const uint32_t w_off = w_base + (uint32_t)(nb * 64 * 64 * 4);
#pragma unroll
            for (int p = 0; p < 4; p++) {
                int r = lr + p * 16;
                cp_async16(a_off + (uint32_t)((r * AS_STRIDE + lc) * 4),
                           &X[(size_t)(row0 + r) * DD + k1 + lc]);
            }
#pragma unroll
            for (int p = 0; p < 4; p++) {
                int kk = lr + p * 16;
                cp_async16(w_off + (uint32_t)((kk * 64 + lc) * 4),
                           &W[(size_t)(k1 + kk) * EE + lc]);
            }
            asm volatile("cp.async.commit_group;");
        }

        const float* A  = sA + buf * 64 * AS_STRIDE;
        const float* Bm = sW + buf * 64 * 64;
#pragma unroll
        for (int kk = 0; kk < 64; kk += 2) {
            float4 b0 = *(const float4*)&Bm[(kk + 0) * 64 + tx * 4];
            float4 b1 = *(const float4*)&Bm[(kk + 1) * 64 + tx * 4];
#pragma unroll
            for (int i = 0; i < 4; i++) {
                float2 a = *(const float2*)&A[(ty * 4 + i) * AS_STRIDE + kk];
                acc[i][0] += a.x * b0.x; acc[i][1] += a.x * b0.y;
                acc[i][2] += a.x * b0.z; acc[i][3] += a.x * b0.w;
                acc[i][0] += a.y * b1.x; acc[i][1] += a.y * b1.y;
                acc[i][2] += a.y * b1.z; acc[i][3] += a.y * b1.w;
            }
        }
        __syncthreads();
    }

    float* L = sW;
#pragma unroll
    for (int i = 0; i < 4; i++) {
        int r   = ty * 4 + i;
        int row = row0 + r;
#pragma unroll
        for (int j = 0; j < 4; j++) {
            int e = tx * 4 + j;
            L[r * 64 + e] = acc[i][j] + noise[(size_t)row * EE + e] * NOISE_SCALE;
        }
    }
    __syncthreads();

    if (tid < 64) {
        int r   = tid;
        int row = row0 + r;
        int b   = row / SS;
        int s   = row % SS;
        float m = -1e30f;
#pragma unroll
        for (int e = 0; e < EE; e++) m = fmaxf(m, L[r * 64 + e]);
        float sum = 0.0f;
#pragma unroll
        for (int e = 0; e < EE; e++) {
            float t = expf(L[r * 64 + e] - m);
            L[r * 64 + e] = t;
            sum += t;
        }
        float inv = 1.0f / sum;
#pragma unroll
        for (int e = 0; e < EE; e++) {
            g_gatesT[((size_t)b * EE + e) * SS + s] = L[r * 64 + e] * inv;
        }
    }
}

// ---------------------------------------------------------------------------
// Kernel 2: register-resident top-64. Each of 512 threads holds 4 u64 keys
// (gate_bits<<32)|~idx in registers. MSD radix select with warp-shuffle
// suffix scan (no keys[] smem array, ~5 syncs per digit iteration), then
// adaptive bitonic sort of <=512 candidates, scatter.
// ---------------------------------------------------------------------------
__global__ __launch_bounds__(512)
void topk_kernel(float* __restrict__ mask_out,
                 float* __restrict__ comb_out)
{
    __shared__ unsigned long long cand[512];
    __shared__ int hist[256];
    __shared__ int warpsum[8], woff[8];
    __shared__ unsigned long long s_prefix, s_thresh;
    __shared__ int s_need, s_done, s_cnt;

    const int tid  = threadIdx.x;
    const int lane = tid & 31;
    const int wrp  = tid >> 5;
    const int b = blockIdx.x >> 6;
    const int e = blockIdx.x & 63;

    // Load 4 keys into registers (coalesced).
    unsigned long long k[4];
    const float* col = &g_gatesT[((size_t)b * EE + e) * SS];
#pragma unroll
    for (int j = 0; j < 4; j++) {
        int i = tid + j * 512;
        unsigned int fb = __float_as_uint(col[i]);   // softmax gates > 0
        k[j] = ((unsigned long long)fb << 32) | (unsigned int)(~i);
    }
    if (tid == 0) { s_done = 0; s_need = CC; s_prefix = 0ULL; }
    __syncthreads();

    // MSD radix select, 8-bit digits; candidate set exits at <= 512.
    for (int shift = 56; shift >= 0; shift -= 8) {
        if (s_done) break;
        const unsigned long long pf = s_prefix;
        const int need = s_need;
        if (tid < 256) hist[tid] = 0;
        __syncthreads();
#pragma unroll
        for (int j = 0; j < 4; j++) {
            bool active = (shift == 56) || ((k[j] >> (shift + 8)) == pf);
            if (active) atomicAdd(&hist[(int)((k[j] >> shift) & 255)], 1);
        }
        __syncthreads();

        // Suffix scan of 256 bins: warp-shuffle intra-warp + 8 warp totals.
        int own = 0, sfx = 0;
        if (tid < 256) {
            own = hist[tid];
            int v = own;
#pragma unroll
            for (int off = 1; off < 32; off <<= 1) {
                int t = __shfl_down_sync(0xFFFFFFFFu, v, off);
                if (lane + off < 32) v += t;
            }
            if (lane == 0) warpsum[wrp] = v;   // total of this warp's 32 bins
            sfx = v;                            // suffix within warp (incl)
        }
        __syncthreads();
        if (tid < 8) {
            // exclusive suffix over warp totals
            int acc = 0;
            for (int w = 7; w > tid; w--) acc += warpsum[w];
            woff[tid] = acc;
        }
        __syncthreads();

        if (tid < 256) {
            int c     = sfx + woff[wrp];        // count of keys with digit >= tid
            int above = c - own;                // strictly greater digit
            if (c >= need && above < need) {
                int got = (CC - need) + c;      // keys >= boundary globally
                unsigned long long np = (pf << 8) | (unsigned long long)tid;
                if (got <= 512 || shift == 0) {
                    s_thresh = np << shift;
                    s_done = 1;
                } else {
                    s_need = need - above;
                    s_prefix = np;
                }
            }
        }
        __syncthreads();
    }

    // Collect candidates (>= threshold) from registers; pad with 0.
    cand[tid] = 0ULL;
    if (tid == 0) s_cnt = 0;
    __syncthreads();
    {
        const unsigned long long T = s_thresh;
#pragma unroll
        for (int j = 0; j < 4; j++) {
            if (k[j] >= T) {
                int p = atomicAdd(&s_cnt, 1);
                if (p < 512) cand[p] = k[j];
            }
        }
    }
    __syncthreads();

    // Adaptive bitonic sort (descending): nsort = next pow2 >= max(cnt, 64).
    int cnt = s_cnt;
    int nsort = 64;
    while (nsort < cnt && nsort < 512) nsort <<= 1;

    for (int k2 = 2; k2 <= nsort; k2 <<= 1) {
        for (int j = k2 >> 1; j > 0; j >>= 1) {
            if (tid < (nsort >> 1)) {
                int i   = ((tid & ~(j - 1)) << 1) | (tid & (j - 1));
                int ixj = i | j;
                bool desc = ((i & k2) == 0);
                unsigned long long a = cand[i];
                unsigned long long c = cand[ixj];
                if ((a < c) == desc) { cand[i] = c; cand[ixj] = a; }
            }
            __syncthreads();
        }
    }

    // Scatter top-64 (rank = c)
    if (tid < CC) {
        unsigned long long kk = cand[tid];
        int   s = (int)(~(unsigned int)kk);
        float v = __uint_as_float((unsigned int)(kk >> 32));
        size_t idx = ((((size_t)b * SS + s) * EE + e) << 6) + tid;
        mask_out[idx] = 1.0f;
        comb_out[idx] = v;
    }
}

// ---------------------------------------------------------------------------
// Launch: memset forked on a side stream (only true dependency is
// memset -> topk scatter); gemm on main stream; join; topk.
// R3 evidence: fork worst-case = exact serial sum (no penalty).
// ---------------------------------------------------------------------------
static cudaStream_t g_s2;
static cudaEvent_t  g_evFork, g_evJoin;
static bool         g_init = false;

extern "C" void kernel_launch(void* const* d_in, const int* in_sizes, int n_in,
                              void* d_out, int out_size)
{
    const float* X     = (const float*)d_in[0];   // [B,S,D]
    const float* W     = (const float*)d_in[1];   // [D,E]
    const float* noise = (const float*)d_in[2];   // [B,S,E]
    float* out = (float*)d_out;

    if (!g_init) {
        cudaStreamCreateWithFlags(&g_s2, cudaStreamNonBlocking);
        cudaEventCreateWithFlags(&g_evFork, cudaEventDisableTiming);
        cudaEventCreateWithFlags(&g_evJoin, cudaEventDisableTiming);
        cudaFuncSetAttribute(gemm_softmax_kernel,
                             cudaFuncAttributeMaxDynamicSharedMemorySize, SMEM_BYTES);
        g_init = true;
    }

    cudaEventRecord(g_evFork, 0);
    cudaStreamWaitEvent(g_s2, g_evFork, 0);
    cudaMemsetAsync(out, 0, (size_t)out_size * sizeof(float), g_s2);

    gemm_softmax_kernel<<<ROWS / 64, 256, SMEM_BYTES>>>(X, W, noise);

    cudaEventRecord(g_evJoin, g_s2);
    cudaStreamWaitEvent(0, g_evJoin, 0);

    topk_kernel<<<BB * EE, 512>>>(out, out + HALF);
}

// round 13
// speedup vs baseline: 1.6698x; 1.6698x over previous
#include <cuda_runtime.h>
#include <stdint.h>

#define BB 4
#define SS 2048
#define DD 1024
#define EE 64
#define CC 64
#define ROWS (BB*SS)          // 8192
#define NOISE_SCALE (1.0f/64.0f)
#define HALF ((size_t)BB*SS*EE*CC)      // elements per output array

// Dynamic smem layout for gemm (floats):
#define AS_STRIDE 68
#define AS_FLOATS (2*64*AS_STRIDE)      // 8704
#define WS_FLOATS (2*64*64)             // 8192
#define SMEM_FLOATS (AS_FLOATS + WS_FLOATS)
#define SMEM_BYTES (SMEM_FLOATS*4)      // 67584

// Scratch: gates transposed [b][e][s]  (2 MB)
__device__ float g_gatesT[(size_t)BB*EE*SS];

__device__ __forceinline__ void cp_async16(uint32_t dst_smem, const void* src) {
    asm volatile("cp.async.cg.shared.global [%0], [%1], 16;" :: "r"(dst_smem), "l"(src));
}

// ---------------------------------------------------------------------------
// Kernel 1: GEMM + noise + softmax -> gatesT. EXACT R11 win kernel:
// 64x64 tile, 4x4 thread tile, k ascending single accumulator (gates
// bit-identical to the reference ranking), cp.async double-buffered tiles.
// ---------------------------------------------------------------------------
__global__ __launch_bounds__(256)
void gemm_softmax_kernel(const float* __restrict__ X,
                         const float* __restrict__ W,
                         const float* __restrict__ noise)
{
    extern __shared__ float smem[];
    float* sA = smem;               // [2][64][AS_STRIDE]
    float* sW = smem + AS_FLOATS;   // [2][64][64]

    const int tid  = threadIdx.x;
    const int tx   = tid & 15;
    const int ty   = tid >> 4;
    const int row0 = blockIdx.x * 64;

    uint32_t smem_u32 = (uint32_t)__cvta_generic_to_shared(smem);
    const uint32_t a_base = smem_u32;
    const uint32_t w_base = smem_u32 + AS_FLOATS * 4;

    const int lr = tid >> 4;
    const int lc = (tid & 15) * 4;

    {
        const int k0 = 0;
#pragma unroll
        for (int p = 0; p < 4; p++) {
            int r = lr + p * 16;
            cp_async16(a_base + (uint32_t)((r * AS_STRIDE + lc) * 4),
                       &X[(size_t)(row0 + r) * DD + k0 + lc]);
        }
#pragma unroll
        for (int p = 0; p < 4; p++) {
            int kk = lr + p * 16;
            cp_async16(w_base + (uint32_t)((kk * 64 + lc) * 4),
                       &W[(size_t)(k0 + kk) * EE + lc]);
        }
        asm volatile("cp.async.commit_group;");
    }

    float acc[4][4];
#pragma unroll
    for (int i = 0; i < 4; i++)
#pragma unroll
        for (int j = 0; j < 4; j++) acc[i][j] = 0.0f;

    for (int it = 0; it < 16; it++) {
        const int buf = it & 1;

        asm volatile("cp.async.wait_group 0;");
        __syncthreads();

        if (it < 15) {
            const int k1 = (it + 1) * 64;
            const int nb = buf ^ 1;
            const uint32_t a_off = a_base + (uint32_t)(nb * 64 * AS_STRIDE * 4);
            const uint32_t w_off = w_base + (uint32_t)(nb * 64 * 64 * 4);
#pragma unroll
            for (int p = 0; p < 4; p++) {
                int r = lr + p * 16;
                cp_async16(a_off + (uint32_t)((r * AS_STRIDE + lc) * 4),
                           &X[(size_t)(row0 + r) * DD + k1 + lc]);
            }
#pragma unroll
            for (int p = 0; p < 4; p++) {
                int kk = lr + p * 16;
                cp_async16(w_off + (uint32_t)((kk * 64 + lc) * 4),
                           &W[(size_t)(k1 + kk) * EE + lc]);
            }
            asm volatile("cp.async.commit_group;");
        }

        const float* A  = sA + buf * 64 * AS_STRIDE;
        const float* Bm = sW + buf * 64 * 64;
#pragma unroll
        for (int kk = 0; kk < 64; kk += 2) {
            float4 b0 = *(const float4*)&Bm[(kk + 0) * 64 + tx * 4];
            float4 b1 = *(const float4*)&Bm[(kk + 1) * 64 + tx * 4];
#pragma unroll
            for (int i = 0; i < 4; i++) {
                float2 a = *(const float2*)&A[(ty * 4 + i) * AS_STRIDE + kk];
                acc[i][0] += a.x * b0.x; acc[i][1] += a.x * b0.y;
                acc[i][2] += a.x * b0.z; acc[i][3] += a.x * b0.w;
                acc[i][0] += a.y * b1.x; acc[i][1] += a.y * b1.y;
                acc[i][2] += a.y * b1.z; acc[i][3] += a.y * b1.w;
            }
        }
        __syncthreads();
    }

    float* L = sW;
#pragma unroll
    for (int i = 0; i < 4; i++) {
        int r   = ty * 4 + i;
        int row = row0 + r;
#pragma unroll
        for (int j = 0; j < 4; j++) {
            int e = tx * 4 + j;
            L[r * 64 + e] = acc[i][j] + noise[(size_t)row * EE + e] * NOISE_SCALE;
        }
    }
    __syncthreads();

    if (tid < 64) {
        int r   = tid;
        int row = row0 + r;
        int b   = row / SS;
        int s   = row % SS;
        float m = -1e30f;
#pragma unroll
        for (int e = 0; e < EE; e++) m = fmaxf(m, L[r * 64 + e]);
        float sum = 0.0f;
#pragma unroll
        for (int e = 0; e < EE; e++) {
            float t = expf(L[r * 64 + e] - m);
            L[r * 64 + e] = t;
            sum += t;
        }
        float inv = 1.0f / sum;
#pragma unroll
        for (int e = 0; e < EE; e++) {
            g_gatesT[((size_t)b * EE + e) * SS + s] = L[r * 64 + e] * inv;
        }
    }
}

// ---------------------------------------------------------------------------
// Kernel 2: register-resident top-64 (measured 9.7us). Each of 512 threads
// holds 4 u64 keys (gate_bits<<32)|~idx. MSD radix select with warp-shuffle
// suffix scan, adaptive bitonic sort of <=512 candidates, scatter.
// ---------------------------------------------------------------------------
__global__ __launch_bounds__(512)
void topk_kernel(float* __restrict__ mask_out,
                 float* __restrict__ comb_out)
{
    __shared__ unsigned long long cand[512];
    __shared__ int hist[256];
    __shared__ int warpsum[8], woff[8];
    __shared__ unsigned long long s_prefix, s_thresh;
    __shared__ int s_need, s_done, s_cnt;

    const int tid  = threadIdx.x;
    const int lane = tid & 31;
    const int wrp  = tid >> 5;
    const int b = blockIdx.x >> 6;
    const int e = blockIdx.x & 63;

    unsigned long long k[4];
    const float* col = &g_gatesT[((size_t)b * EE + e) * SS];
#pragma unroll
    for (int j = 0; j < 4; j++) {
        int i = tid + j * 512;
        unsigned int fb = __float_as_uint(col[i]);   // softmax gates > 0
        k[j] = ((unsigned long long)fb << 32) | (unsigned int)(~i);
    }
    if (tid == 0) { s_done = 0; s_need = CC; s_prefix = 0ULL; }
    __syncthreads();

    for (int shift = 56; shift >= 0; shift -= 8) {
        if (s_done) break;
        const unsigned long long pf = s_prefix;
        const int need = s_need;
        if (tid < 256) hist[tid] = 0;
        __syncthreads();
#pragma unroll
        for (int j = 0; j < 4; j++) {
            bool active = (shift == 56) || ((k[j] >> (shift + 8)) == pf);
            if (active) atomicAdd(&hist[(int)((k[j] >> shift) & 255)], 1);
        }
        __syncthreads();

        int own = 0, sfx = 0;
        if (tid < 256) {
            own = hist[tid];
            int v = own;
#pragma unroll
            for (int off = 1; off < 32; off <<= 1) {
                int t = __shfl_down_sync(0xFFFFFFFFu, v, off);
                if (lane + off < 32) v += t;
            }
            if (lane == 0) warpsum[wrp] = v;
            sfx = v;
        }
        __syncthreads();
        if (tid < 8) {
            int acc = 0;
            for (int w = 7; w > tid; w--) acc += warpsum[w];
            woff[tid] = acc;
        }
        __syncthreads();

        if (tid < 256) {
            int c     = sfx + woff[wrp];
            int above = c - own;
            if (c >= need && above < need) {
                int got = (CC - need) + c;
                unsigned long long np = (pf << 8) | (unsigned long long)tid;
                if (got <= 512 || shift == 0) {
                    s_thresh = np << shift;
                    s_done = 1;
                } else {
                    s_need = need - above;
                    s_prefix = np;
                }
            }
        }
        __syncthreads();
    }

    cand[tid] = 0ULL;
    if (tid == 0) s_cnt = 0;
    __syncthreads();
    {
        const unsigned long long T = s_thresh;
#pragma unroll
        for (int j = 0; j < 4; j++) {
            if (k[j] >= T) {
                int p = atomicAdd(&s_cnt, 1);
                if (p < 512) cand[p] = k[j];
            }
        }
    }
    __syncthreads();

    int cnt = s_cnt;
    int nsort = 64;
    while (nsort < cnt && nsort < 512) nsort <<= 1;

    for (int k2 = 2; k2 <= nsort; k2 <<= 1) {
        for (int j = k2 >> 1; j > 0; j >>= 1) {
            if (tid < (nsort >> 1)) {
                int i   = ((tid & ~(j - 1)) << 1) | (tid & (j - 1));
                int ixj = i | j;
                bool desc = ((i & k2) == 0);
                unsigned long long a = cand[i];
                unsigned long long c = cand[ixj];
                if ((a < c) == desc) { cand[i] = c; cand[ixj] = a; }
            }
            __syncthreads();
        }
    }

    if (tid < CC) {
        unsigned long long kk = cand[tid];
        int   s = (int)(~(unsigned int)kk);
        float v = __uint_as_float((unsigned int)(kk >> 32));
        size_t idx = ((((size_t)b * SS + s) * EE + e) << 6) + tid;
        mask_out[idx] = 1.0f;
        comb_out[idx] = v;
    }
}

// ---------------------------------------------------------------------------
// STRICTLY SERIAL pipeline (R12 proved even driver-memset concurrency
// regresses): memset -> gemm -> topk, single stream.
// ---------------------------------------------------------------------------
extern "C" void kernel_launch(void* const* d_in, const int* in_sizes, int n_in,
                              void* d_out, int out_size)
{
    const float* X     = (const float*)d_in[0];   // [B,S,D]
    const float* W     = (const float*)d_in[1];   // [D,E]
    const float* noise = (const float*)d_in[2];   // [B,S,E]
    float* out = (float*)d_out;

    cudaFuncSetAttribute(gemm_softmax_kernel,
                         cudaFuncAttributeMaxDynamicSharedMemorySize, SMEM_BYTES);

    cudaMemsetAsync(out, 0, (size_t)out_size * sizeof(float), 0);
    gemm_softmax_kernel<<<ROWS / 64, 256, SMEM_BYTES>>>(X, W, noise);
    topk_kernel<<<BB * EE, 512>>>(out, out + HALF);
}

// round 14
// speedup vs baseline: 1.7014x; 1.0189x over previous
#include <cuda_runtime.h>
#include <stdint.h>

#define BB 4
#define SS 2048
#define DD 1024
#define EE 64
#define CC 64
#define ROWS (BB*SS)          // 8192
#define NOISE_SCALE (1.0f/64.0f)
#define HALF ((size_t)BB*SS*EE*CC)      // elements per output array

// Dynamic smem layout for gemm (floats):
#define AS_STRIDE 68
#define AS_FLOATS (2*64*AS_STRIDE)      // 8704
#define WS_FLOATS (2*64*64)             // 8192
#define SMEM_FLOATS (AS_FLOATS + WS_FLOATS)
#define SMEM_BYTES (SMEM_FLOATS*4)      // 67584

// Scratch: gates transposed [b][e][s]  (2 MB)
__device__ float g_gatesT[(size_t)BB*EE*SS];

__device__ __forceinline__ void cp_async16(uint32_t dst_smem, const void* src) {
    asm volatile("cp.async.cg.shared.global [%0], [%1], 16;" :: "r"(dst_smem), "l"(src));
}

__device__ __forceinline__ float2 ffma2(float2 a, float2 b, float2 c) {
    unsigned long long au = *reinterpret_cast<unsigned long long*>(&a);
    unsigned long long bu = *reinterpret_cast<unsigned long long*>(&b);
    unsigned long long cu = *reinterpret_cast<unsigned long long*>(&c);
    unsigned long long du;
    asm("fma.rn.f32x2 %0, %1, %2, %3;" : "=l"(du) : "l"(au), "l"(bu), "l"(cu));
    return *reinterpret_cast<float2*>(&du);
}

// ---------------------------------------------------------------------------
// Kernel 1: GEMM + noise + softmax -> gatesT.
// R11/R13 skeleton (cp.async double-buffered 64x64 tiles, 4x4 thread tile),
// inner loop upgraded to fma.rn.f32x2: 2 experts per FFMA2 lane-pair.
// Per-output accumulation stays single-lane, k-ascending -> gates remain
// bit-identical to the reference ranking (rel_err 1.346339e-07).
// ---------------------------------------------------------------------------
__global__ __launch_bounds__(256)
void gemm_softmax_kernel(const float* __restrict__ X,
                         const float* __restrict__ W,
                         const float* __restrict__ noise)
{
    extern __shared__ float smem[];
    float* sA = smem;               // [2][64][AS_STRIDE]
    float* sW = smem + AS_FLOATS;   // [2][64][64]

    const int tid  = threadIdx.x;
    const int tx   = tid & 15;
    const int ty   = tid >> 4;
    const int row0 = blockIdx.x * 64;

    uint32_t smem_u32 = (uint32_t)__cvta_generic_to_shared(smem);
    const uint32_t a_base = smem_u32;
    const uint32_t w_base = smem_u32 + AS_FLOATS * 4;

    const int lr = tid >> 4;
    const int lc = (tid & 15) * 4;

    {
        const int k0 = 0;
#pragma unroll
        for (int p = 0; p < 4; p++) {
            int r = lr + p * 16;
            cp_async16(a_base + (uint32_t)((r * AS_STRIDE + lc) * 4),
                       &X[(size_t)(row0 + r) * DD + k0 + lc]);
        }
#pragma unroll
        for (int p = 0; p < 4; p++) {
            int kk = lr + p * 16;
            cp_async16(w_base + (uint32_t)((kk * 64 + lc) * 4),
                       &W[(size_t)(k0 + kk) * EE + lc]);
        }
        asm volatile("cp.async.commit_group;");
    }

    // Accumulators: 4 rows x 2 expert-pairs (float2) = experts tx*4 .. tx*4+3
    float2 acc[4][2];
#pragma unroll
    for (int i = 0; i < 4; i++) {
        acc[i][0] = make_float2(0.f, 0.f);
        acc[i][1] = make_float2(0.f, 0.f);
    }

    for (int it = 0; it < 16; it++) {
        const int buf = it & 1;

        asm volatile("cp.async.wait_group 0;");
        __syncthreads();

        if (it < 15) {
            const int k1 = (it + 1) * 64;
            const int nb = buf ^ 1;
            const uint32_t a_off = a_base + (uint32_t)(nb * 64 * AS_STRIDE * 4);
            const uint32_t w_off = w_base + (uint32_t)(nb * 64 * 64 * 4);
#pragma unroll
            for (int p = 0; p < 4; p++) {
                int r = lr + p * 16;
                cp_async16(a_off + (uint32_t)((r * AS_STRIDE + lc) * 4),
                           &X[(size_t)(row0 + r) * DD + k1 + lc]);
            }
#pragma unroll
            for (int p = 0; p < 4; p++) {
                int kk = lr + p * 16;
                cp_async16(w_off + (uint32_t)((kk * 64 + lc) * 4),
                           &W[(size_t)(k1 + kk) * EE + lc]);
            }
            asm volatile("cp.async.commit_group;");
        }

        const float* A  = sA + buf * 64 * AS_STRIDE;
        const float* Bm = sW + buf * 64 * 64;
#pragma unroll
        for (int kk = 0; kk < 64; kk += 2) {
            // B for experts tx*4..tx*4+3 at k=kk and k=kk+1
            float4 bq0 = *(const float4*)&Bm[(kk + 0) * 64 + tx * 4];
            float4 bq1 = *(const float4*)&Bm[(kk + 1) * 64 + tx * 4];
            float2 b0p01 = make_float2(bq0.x, bq0.y);
            float2 b0p23 = make_float2(bq0.z, bq0.w);
            float2 b1p01 = make_float2(bq1.x, bq1.y);
            float2 b1p23 = make_float2(bq1.z, bq1.w);
#pragma unroll
            for (int i = 0; i < 4; i++) {
                float2 av  = *(const float2*)&A[(ty * 4 + i) * AS_STRIDE + kk];
                float2 axx = make_float2(av.x, av.x);
                float2 ayy = make_float2(av.y, av.y);
                // k = kk first, then kk+1: per-lane k-ascending accumulation
                acc[i][0] = ffma2(axx, b0p01, acc[i][0]);
                acc[i][1] = ffma2(axx, b0p23, acc[i][1]);
                acc[i][0] = ffma2(ayy, b1p01, acc[i][0]);
                acc[i][1] = ffma2(ayy, b1p23, acc[i][1]);
            }
        }
        __syncthreads();
    }

    float* L = sW;
#pragma unroll
    for (int i = 0; i < 4; i++) {
        int r   = ty * 4 + i;
        int row = row0 + r;
        int e0  = tx * 4;
        L[r * 64 + e0 + 0] = acc[i][0].x + noise[(size_t)row * EE + e0 + 0] * NOISE_SCALE;
        L[r * 64 + e0 + 1] = acc[i][0].y + noise[(size_t)row * EE + e0 + 1] * NOISE_SCALE;
        L[r * 64 + e0 + 2] = acc[i][1].x + noise[(size_t)row * EE + e0 + 2] * NOISE_SCALE;
        L[r * 64 + e0 + 3] = acc[i][1].y + noise[(size_t)row * EE + e0 + 3] * NOISE_SCALE;
    }
    __syncthreads();

    if (tid < 64) {
        int r   = tid;
        int row = row0 + r;
        int b   = row / SS;
        int s   = row % SS;
        float m = -1e30f;
#pragma unroll
        for (int e = 0; e < EE; e++) m = fmaxf(m, L[r * 64 + e]);
        float sum = 0.0f;
#pragma unroll
        for (int e = 0; e < EE; e++) {
            float t = expf(L[r * 64 + e] - m);
            L[r * 64 + e] = t;
            sum += t;
        }
        float inv = 1.0f / sum;
#pragma unroll
        for (int e = 0; e < EE; e++) {
            g_gatesT[((size_t)b * EE + e) * SS + s] = L[r * 64 + e] * inv;
        }
    }
}

// ---------------------------------------------------------------------------
// Kernel 2: register-resident top-64 (unchanged from R13 win).
// ---------------------------------------------------------------------------
__global__ __launch_bounds__(512)
void topk_kernel(float* __restrict__ mask_out,
                 float* __restrict__ comb_out)
{
    __shared__ unsigned long long cand[512];
    __shared__ int hist[256];
    __shared__ int warpsum[8], woff[8];
    __shared__ unsigned long long s_prefix, s_thresh;
    __shared__ int s_need, s_done, s_cnt;

    const int tid  = threadIdx.x;
    const int lane = tid & 31;
    const int wrp  = tid >> 5;
    const int b = blockIdx.x >> 6;
    const int e = blockIdx.x & 63;

    unsigned long long k[4];
    const float* col = &g_gatesT[((size_t)b * EE + e) * SS];
#pragma unroll
    for (int j = 0; j < 4; j++) {
        int i = tid + j * 512;
        unsigned int fb = __float_as_uint(col[i]);   // softmax gates > 0
        k[j] = ((unsigned long long)fb << 32) | (unsigned int)(~i);
    }
    if (tid == 0) { s_done = 0; s_need = CC; s_prefix = 0ULL; }
    __syncthreads();

    for (int shift = 56; shift >= 0; shift -= 8) {
        if (s_done) break;
        const unsigned long long pf = s_prefix;
        const int need = s_need;
        if (tid < 256) hist[tid] = 0;
        __syncthreads();
#pragma unroll
        for (int j = 0; j < 4; j++) {
            bool active = (shift == 56) || ((k[j] >> (shift + 8)) == pf);
            if (active) atomicAdd(&hist[(int)((k[j] >> shift) & 255)], 1);
        }
        __syncthreads();

        int own = 0, sfx = 0;
        if (tid < 256) {
            own = hist[tid];
            int v = own;
#pragma unroll
            for (int off = 1; off < 32; off <<= 1) {
                int t = __shfl_down_sync(0xFFFFFFFFu, v, off);
                if (lane + off < 32) v += t;
            }
            if (lane == 0) warpsum[wrp] = v;
            sfx = v;
        }
        __syncthreads();
        if (tid < 8) {
            int acc = 0;
            for (int w = 7; w > tid; w--) acc += warpsum[w];
            woff[tid] = acc;
        }
        __syncthreads();

        if (tid < 256) {
            int c     = sfx + woff[wrp];
            int above = c - own;
            if (c >= need && above < need) {
                int got = (CC - need) + c;
                unsigned long long np = (pf << 8) | (unsigned long long)tid;
                if (got <= 512 || shift == 0) {
                    s_thresh = np << shift;
                    s_done = 1;
                } else {
                    s_need = need - above;
                    s_prefix = np;
                }
            }
        }
        __syncthreads();
    }

    cand[tid] = 0ULL;
    if (tid == 0) s_cnt = 0;
    __syncthreads();
    {
        const unsigned long long T = s_thresh;
#pragma unroll
        for (int j = 0; j < 4; j++) {
            if (k[j] >= T) {
                int p = atomicAdd(&s_cnt, 1);
                if (p < 512) cand[p] = k[j];
            }
        }
    }
    __syncthreads();

    int cnt = s_cnt;
    int nsort = 64;
    while (nsort < cnt && nsort < 512) nsort <<= 1;

    for (int k2 = 2; k2 <= nsort; k2 <<= 1) {
        for (int j = k2 >> 1; j > 0; j >>= 1) {
            if (tid < (nsort >> 1)) {
                int i   = ((tid & ~(j - 1)) << 1) | (tid & (j - 1));
                int ixj = i | j;
                bool desc = ((i & k2) == 0);
                unsigned long long a = cand[i];
                unsigned long long c = cand[ixj];
                if ((a < c) == desc) { cand[i] = c; cand[ixj] = a; }
            }
            __syncthreads();
        }
    }

    if (tid < CC) {
        unsigned long long kk = cand[tid];
        int   s = (int)(~(unsigned int)kk);
        float v = __uint_as_float((unsigned int)(kk >> 32));
        size_t idx = ((((size_t)b * SS + s) * EE + e) << 6) + tid;
        mask_out[idx] = 1.0f;
        comb_out[idx] = v;
    }
}

// ---------------------------------------------------------------------------
// STRICTLY SERIAL pipeline: memset -> gemm -> topk, single stream.
// ---------------------------------------------------------------------------
extern "C" void kernel_launch(void* const* d_in, const int* in_sizes, int n_in,
                              void* d_out, int out_size)
{
    const float* X     = (const float*)d_in[0];   // [B,S,D]
    const float* W     = (const float*)d_in[1];   // [D,E]
    const float* noise = (const float*)d_in[2];   // [B,S,E]
    float* out = (float*)d_out;

    cudaFuncSetAttribute(gemm_softmax_kernel,
                         cudaFuncAttributeMaxDynamicSharedMemorySize, SMEM_BYTES);

    cudaMemsetAsync(out, 0, (size_t)out_size * sizeof(float), 0);
    gemm_softmax_kernel<<<ROWS / 64, 256, SMEM_BYTES>>>(X, W, noise);
    topk_kernel<<<BB * EE, 512>>>(out, out + HALF);
}